// round 1
// baseline (speedup 1.0000x reference)
#include <cuda_runtime.h>
#include <cstdint>

#define BV   16
#define TV   2048
#define INV  80
#define HV   512
#define DV   512
#define KV   1024
#define ROWS (BV * TV)   // 32768

// ---------------- scratch (device globals; no allocation allowed) ----------
__device__ float g_bufA[(size_t)ROWS * HV];   // 64 MB
__device__ float g_bufB[(size_t)ROWS * HV];   // 64 MB
__device__ float g_cnorm[KV];
__device__ float g_idx_dummy[ROWS];           // fallback if out has no idx region

// ---------------- helpers --------------------------------------------------
__device__ __forceinline__ unsigned ford(float f) {
    unsigned u = __float_as_uint(f);
    return (u & 0x80000000u) ? ~u : (u | 0x80000000u);
}

// ---------------- codebook squared norms -----------------------------------
__global__ void cnorm_kernel(const float* __restrict__ cb, float* __restrict__ cn) {
    int k = blockIdx.x * 8 + (threadIdx.x >> 5);
    int lane = threadIdx.x & 31;
    float s = 0.f;
    const float* row = cb + (size_t)k * DV;
    #pragma unroll
    for (int c = lane; c < DV; c += 32) { float v = row[c]; s += v * v; }
    #pragma unroll
    for (int o = 16; o; o >>= 1) s += __shfl_xor_sync(0xFFFFFFFFu, s, o);
    if (lane == 0) cn[k] = s;
}

// ---------------- conv1d (K=3, SAME) as shifted GEMM -----------------------
// in:  [B, T, CIN] row-major   w: [COUT, CIN, 3]   out: [B, T, OUTSTRIDE]
// block tile: 128 t-rows x 128 cout, TK=16 over CIN; 256 threads, 8x8 micro-tile
template<int CIN, int COUT, int OUTSTRIDE, bool RELU>
__global__ __launch_bounds__(256, 1)
void conv3_kernel(const float* __restrict__ in, const float* __restrict__ w,
                  const float* __restrict__ bias, float* __restrict__ out)
{
    __shared__ float As[130 * 16];          // rows t0-1 .. t0+128, 16 cin
    __shared__ float Ws[3 * 16 * 128];      // [tap][cin][cout]

    const int tid = threadIdx.x;
    const int tx = tid & 15, ty = tid >> 4;
    const int c0 = blockIdx.x * 128;
    const int t0 = blockIdx.y * 128;
    const int b  = blockIdx.z;
    const float* inb = in + (size_t)b * TV * CIN;

    float acc[8][8];
    #pragma unroll
    for (int i = 0; i < 8; i++)
        #pragma unroll
        for (int j = 0; j < 8; j++) acc[i][j] = 0.f;

    for (int ck = 0; ck < CIN; ck += 16) {
        // load input tile (130 x 16), zero-padded at batch edges
        for (int i = tid; i < 130 * 16; i += 256) {
            int r = i >> 4, c = i & 15;
            int t = t0 - 1 + r;
            float v = 0.f;
            if (t >= 0 && t < TV) v = inb[(size_t)t * CIN + ck + c];
            As[i] = v;
        }
        // load weight tile: 128 cout x 16 cin x 3 taps
        for (int j = tid; j < 128 * 48; j += 256) {
            int co  = j / 48;
            int rem = j - co * 48;
            int ci  = rem / 3;
            int d   = rem - ci * 3;
            float v = 0.f;
            if (c0 + co < COUT)
                v = w[(size_t)(c0 + co) * CIN * 3 + (size_t)(ck + ci) * 3 + d];
            Ws[(d * 16 + ci) * 128 + co] = v;
        }
        __syncthreads();

        #pragma unroll
        for (int kk = 0; kk < 16; kk++) {
            float wv[3][8];
            #pragma unroll
            for (int d = 0; d < 3; d++)
                #pragma unroll
                for (int j = 0; j < 8; j++)
                    wv[d][j] = Ws[(d * 16 + kk) * 128 + tx + 16 * j];
            #pragma unroll
            for (int i = 0; i < 8; i++) {
                int r = ty + 16 * i;
                float a0 = As[(r    ) * 16 + kk];
                float a1 = As[(r + 1) * 16 + kk];
                float a2 = As[(r + 2) * 16 + kk];
                #pragma unroll
                for (int j = 0; j < 8; j++)
                    acc[i][j] += a0 * wv[0][j] + a1 * wv[1][j] + a2 * wv[2][j];
            }
        }
        __syncthreads();
    }

    // epilogue: bias (+ReLU) + store
    #pragma unroll
    for (int j = 0; j < 8; j++) {
        int col = c0 + tx + 16 * j;
        if (col < COUT) {
            float bv = bias[col];
            #pragma unroll
            for (int i = 0; i < 8; i++) {
                int t = t0 + ty + 16 * i;
                float v = acc[i][j] + bv;
                if (RELU) v = fmaxf(v, 0.f);
                out[((size_t)b * TV + t) * OUTSTRIDE + col] = v;
            }
        }
    }
}

// ---------------- VQ: argmin_k (||c_k||^2 - 2 z.c_k) + gather --------------
// z: [ROWS, DV]; block handles 128 rows, loops all K in 128-code tiles.
__global__ __launch_bounds__(256, 1)
void vq_kernel(const float* __restrict__ z, const float* __restrict__ cb,
               const float* __restrict__ cn, float* __restrict__ q,
               float* __restrict__ idx_f)
{
    __shared__ float Zs[128 * 16];
    __shared__ float Cs[16 * 129];          // padded to kill store conflicts
    __shared__ unsigned long long sMin[128];

    const int tid = threadIdx.x;
    const int tx = tid & 15, ty = tid >> 4;
    const int r0 = blockIdx.x * 128;

    float    minv[8];
    unsigned mink[8];
    #pragma unroll
    for (int i = 0; i < 8; i++) { minv[i] = 3.4e38f; mink[i] = 0; }

    for (int k0 = 0; k0 < KV; k0 += 128) {
        float acc[8][8];
        #pragma unroll
        for (int i = 0; i < 8; i++)
            #pragma unroll
            for (int j = 0; j < 8; j++) acc[i][j] = 0.f;

        for (int dd = 0; dd < DV; dd += 16) {
            for (int i = tid; i < 128 * 16; i += 256) {
                int r = i >> 4, c = i & 15;
                Zs[i] = z[(size_t)(r0 + r) * DV + dd + c];
            }
            for (int i = tid; i < 128 * 16; i += 256) {
                int k = i >> 4, c = i & 15;      // coalesced global read
                Cs[c * 129 + k] = cb[(size_t)(k0 + k) * DV + dd + c];
            }
            __syncthreads();

            #pragma unroll
            for (int kk = 0; kk < 16; kk++) {
                float zr[8], cr[8];
                #pragma unroll
                for (int i = 0; i < 8; i++) zr[i] = Zs[(ty + 16 * i) * 16 + kk];
                #pragma unroll
                for (int j = 0; j < 8; j++) cr[j] = Cs[kk * 129 + tx + 16 * j];
                #pragma unroll
                for (int i = 0; i < 8; i++)
                    #pragma unroll
                    for (int j = 0; j < 8; j++) acc[i][j] += zr[i] * cr[j];
            }
            __syncthreads();
        }

        // fold into running per-row argmin (k ascending -> strict < = first-min)
        #pragma unroll
        for (int j = 0; j < 8; j++) {
            int k = k0 + tx + 16 * j;
            float c2 = cn[k];
            #pragma unroll
            for (int i = 0; i < 8; i++) {
                float dist = c2 - 2.f * acc[i][j];
                if (dist < minv[i]) { minv[i] = dist; mink[i] = (unsigned)k; }
            }
        }
    }

    if (tid < 128) sMin[tid] = ~0ULL;
    __syncthreads();
    #pragma unroll
    for (int i = 0; i < 8; i++) {
        unsigned long long key =
            ((unsigned long long)ford(minv[i]) << 32) | (unsigned long long)mink[i];
        atomicMin(&sMin[ty + 16 * i], key);
    }
    __syncthreads();

    if (tid < 128) {
        unsigned k = (unsigned)(sMin[tid] & 0xFFFFFFFFu);
        idx_f[r0 + tid] = (float)k;
    }
    // gather quantized vectors (coalesced)
    for (int e = tid; e < 128 * DV; e += 256) {
        int r = e >> 9;            // DV = 512
        int c = e & 511;
        unsigned k = (unsigned)(sMin[r] & 0xFFFFFFFFu);
        q[(size_t)(r0 + r) * DV + c] = cb[(size_t)k * DV + c];
    }
}

// ---------------- launch ----------------------------------------------------
extern "C" void kernel_launch(void* const* d_in, const int* in_sizes, int n_in,
                              void* d_out, int out_size)
{
    const float* mels = (const float*)d_in[0];
    const float* ew1  = (const float*)d_in[1];
    const float* eb1  = (const float*)d_in[2];
    const float* ew2  = (const float*)d_in[3];
    const float* eb2  = (const float*)d_in[4];
    const float* cb   = (const float*)d_in[5];
    const float* dw1  = (const float*)d_in[6];
    const float* db1  = (const float*)d_in[7];
    const float* dw2  = (const float*)d_in[8];
    const float* db2  = (const float*)d_in[9];

    float* out = (float*)d_out;

    float *bufA, *bufB, *cn, *idx_dummy;
    cudaGetSymbolAddress((void**)&bufA, g_bufA);
    cudaGetSymbolAddress((void**)&bufB, g_bufB);
    cudaGetSymbolAddress((void**)&cn,   g_cnorm);
    cudaGetSymbolAddress((void**)&idx_dummy, g_idx_dummy);

    float* recon = out;
    float* idx_f = (out_size >= (int)((size_t)ROWS * INV + ROWS))
                     ? out + (size_t)ROWS * INV
                     : idx_dummy;

    cnorm_kernel<<<KV / 8, 256>>>(cb, cn);

    // encoder
    conv3_kernel<INV, HV, HV, true ><<<dim3(HV / 128, TV / 128, BV), 256>>>(mels, ew1, eb1, bufA);
    conv3_kernel<HV,  DV, DV, false><<<dim3(DV / 128, TV / 128, BV), 256>>>(bufA, ew2, eb2, bufB);

    // vector quantization (z in bufB -> q in bufA)
    vq_kernel<<<ROWS / 128, 256>>>(bufB, cb, cn, bufA, idx_f);

    // decoder
    conv3_kernel<DV, HV, HV, true ><<<dim3(HV / 128, TV / 128, BV), 256>>>(bufA, dw1, db1, bufB);
    conv3_kernel<HV, INV, INV, false><<<dim3(1, TV / 128, BV), 256>>>(bufB, dw2, db2, recon);
}

// round 3
// speedup vs baseline: 5.4020x; 5.4020x over previous
#include <cuda_runtime.h>
#include <cuda_fp16.h>
#include <cstdint>

#define BV   16
#define TV   2048
#define INV  80
#define HV   512
#define DV   512
#define KV   1024
#define ROWS (BV * TV)   // 32768

typedef unsigned long long ull;

// ---------------- scratch (device globals; no allocation allowed) ----------
__device__ __half g_mh[(size_t)ROWS * INV];
__device__ __half g_ml[(size_t)ROWS * INV];
__device__ __half g_xh[(size_t)ROWS * DV];
__device__ __half g_xl[(size_t)ROWS * DV];
__device__ __half g_yh[(size_t)ROWS * DV];
__device__ __half g_yl[(size_t)ROWS * DV];
#define OW1 0
#define OW2 131072
#define OW3 917504
#define OW4 1703936
#define WTOT 1826816
__device__ __half g_wh[WTOT];
__device__ __half g_wl[WTOT];
__device__ __half g_cbh[(size_t)KV * DV];
__device__ __half g_cbl[(size_t)KV * DV];
__device__ float  g_cn[KV];
__device__ ull    g_keys[ROWS];
__device__ float  g_idxd[ROWS];

// ---------------- helpers --------------------------------------------------
__device__ __forceinline__ uint32_t smem_u32(const void* p) {
    uint32_t a;
    asm("{ .reg .u64 t; cvta.to.shared.u64 t, %1; cvt.u32.u64 %0, t; }"
        : "=r"(a) : "l"(p));
    return a;
}
__device__ __forceinline__ void ldsm4(uint32_t* r, uint32_t addr) {
    asm volatile("ldmatrix.sync.aligned.m8n8.x4.shared.b16 {%0,%1,%2,%3}, [%4];"
                 : "=r"(r[0]), "=r"(r[1]), "=r"(r[2]), "=r"(r[3]) : "r"(addr));
}
__device__ __forceinline__ void mma16816(float* c, const uint32_t* a, const uint32_t* b) {
    asm volatile(
        "mma.sync.aligned.m16n8k16.row.col.f32.f16.f16.f32 "
        "{%0,%1,%2,%3}, {%4,%5,%6,%7}, {%8,%9}, {%0,%1,%2,%3};"
        : "+f"(c[0]), "+f"(c[1]), "+f"(c[2]), "+f"(c[3])
        : "r"(a[0]), "r"(a[1]), "r"(a[2]), "r"(a[3]), "r"(b[0]), "r"(b[1]));
}
__device__ __forceinline__ unsigned ford(float f) {
    unsigned u = __float_as_uint(f);
    return (u & 0x80000000u) ? ~u : (u | 0x80000000u);
}
__device__ __forceinline__ void h_split(float v, __half& h, __half& l) {
    h = __float2half_rn(v);
    l = __float2half_rn(v - __half2float(h));
}

// ---------------- prep kernels ---------------------------------------------
__global__ void split_arr(const float* __restrict__ x, __half* __restrict__ h,
                          __half* __restrict__ l, size_t n) {
    size_t i = (size_t)blockIdx.x * blockDim.x + threadIdx.x;
    if (i < n) { __half hh, ll; h_split(x[i], hh, ll); h[i] = hh; l[i] = ll; }
}
// w[co][ci][d] -> [co][k=d*CIN+ci] padded to KTP, split
template<int CIN, int COUT, int KTP>
__global__ void prep_w(const float* __restrict__ w, __half* __restrict__ wh,
                       __half* __restrict__ wl) {
    int i = blockIdx.x * 256 + threadIdx.x;
    if (i >= COUT * KTP) return;
    int co = i / KTP, k = i - co * KTP;
    float v = 0.f;
    if (k < 3 * CIN) {
        int d = k / CIN, ci = k - d * CIN;
        v = w[((size_t)co * CIN + ci) * 3 + d];
    }
    __half hh, ll; h_split(v, hh, ll);
    wh[i] = hh; wl[i] = ll;
}
__global__ void cnorm_kernel(const float* __restrict__ cb, float* __restrict__ cn) {
    int k = blockIdx.x * 8 + (threadIdx.x >> 5);
    int lane = threadIdx.x & 31;
    float s = 0.f;
    const float* row = cb + (size_t)k * DV;
    for (int c = lane; c < DV; c += 32) { float v = row[c]; s += v * v; }
    #pragma unroll
    for (int o = 16; o; o >>= 1) s += __shfl_xor_sync(0xFFFFFFFFu, s, o);
    if (lane == 0) cn[k] = s;
}
__global__ void init_keys(ull* k) {
    int i = blockIdx.x * 256 + threadIdx.x;
    if (i < ROWS) k[i] = ~0ULL;
}
__global__ void gather_q(const ull* __restrict__ keys, const __half* __restrict__ cbh,
                         __half* __restrict__ qh, float* __restrict__ idxf) {
    int r0 = blockIdx.x * 128;
    int tid = threadIdx.x;
    if (tid < 128)
        idxf[r0 + tid] = (float)(unsigned)(keys[r0 + tid] & 0xFFFFFFFFu);
    for (int e = tid; e < 128 * DV; e += 256) {
        int r = e >> 9, c = e & 511;
        unsigned k = (unsigned)(keys[r0 + r] & 0xFFFFFFFFu);
        qh[(size_t)(r0 + r) * DV + c] = cbh[(size_t)k * DV + c];
    }
}

// ---------------- mma.sync fp16-split GEMM ----------------------------------
// C[m, n] = sum_k A[m,k] * B[n,k];  A via optional conv im2col (k = d*CIN+ci,
// row shift d-1).  PASSES=3: A0B1 + A0B0 + A1B0 (fp32-accurate split).
// EPI: 0 = bias(+relu) -> split fp16 hi/lo   1 = bias(+relu) -> fp16 hi only
//      2 = bias -> fp32 out (col<NB guard)   3 = VQ argmin (aux = ||c||^2)
template<int CIN, int NB, int KT, int CONV, int PASSES, int EPI, int RELU, int OSTR>
__global__ __launch_bounds__(256)
void mma_gemm(const __half* __restrict__ Ah, const __half* __restrict__ Al,
              const __half* __restrict__ Bh, const __half* __restrict__ Bl,
              const float* __restrict__ aux,
              __half* __restrict__ oh, __half* __restrict__ ol,
              float* __restrict__ of, ull* __restrict__ keys)
{
    constexpr int NCH = (KT + 31) / 32;
    constexpr int KTP = NCH * 32;
    constexpr int LDS = 40;                        // 32 + 8 pad halves
    __shared__ __align__(16) __half As0[128 * LDS];
    __shared__ __align__(16) __half As1[128 * LDS];
    __shared__ __align__(16) __half Bs0[128 * LDS];
    __shared__ __align__(16) __half Bs1[128 * LDS];

    const int tid = threadIdx.x, lane = tid & 31, wid = tid >> 5;
    const int warp_m = (wid & 1) * 64, warp_n = (wid >> 1) * 32;
    const int n0 = blockIdx.x * 128, m0 = blockIdx.y * 128;
    const int bb = CONV ? m0 / TV : 0;
    const int tl = CONV ? m0 % TV : 0;

    float C[4][4][4];
    #pragma unroll
    for (int i = 0; i < 4; i++)
        #pragma unroll
        for (int j = 0; j < 4; j++)
            #pragma unroll
            for (int q = 0; q < 4; q++) C[i][j][q] = 0.f;

    const uint32_t a0b = smem_u32(As0), a1b = smem_u32(As1);
    const uint32_t b0b = smem_u32(Bs0), b1b = smem_u32(Bs1);
    uint32_t aoff[4], boff[2];
    #pragma unroll
    for (int mi = 0; mi < 4; mi++)
        aoff[mi] = ((warp_m + mi * 16 + (lane & 15)) * LDS + (lane >> 4) * 8) * 2;
    #pragma unroll
    for (int bj = 0; bj < 2; bj++)
        boff[bj] = ((warp_n + bj * 16 + ((lane >> 4) << 3) + (lane & 7)) * LDS
                    + ((lane >> 3) & 1) * 8) * 2;

    uint4 va[2][2], vb[2][2];

#define LOADG(cc) do {                                                         \
    _Pragma("unroll")                                                          \
    for (int p = 0; p < 2; p++) {                                              \
        int i_ = tid + p * 256;                                                \
        int r_ = i_ >> 2, v8_ = (i_ & 3) * 8;                                  \
        int k_ = (cc) * 32 + v8_;                                              \
        uint4 hA = make_uint4(0,0,0,0), lA = hA;                               \
        if (KT == KTP || k_ < KT) {                                            \
            int d_ = CONV ? k_ / CIN : 0;                                      \
            int ci_ = k_ - d_ * CIN;                                           \
            bool ok_ = true; size_t row_;                                      \
            if (CONV) { int t_ = tl + r_ + d_ - 1; ok_ = (t_ >= 0 && t_ < TV); \
                        row_ = (size_t)bb * TV + (ok_ ? t_ : 0); }             \
            else row_ = (size_t)(m0 + r_);                                     \
            if (ok_) {                                                         \
                hA = *(const uint4*)(Ah + row_ * CIN + ci_);                   \
                if (PASSES == 3) lA = *(const uint4*)(Al + row_ * CIN + ci_);  \
            }                                                                  \
        }                                                                      \
        va[p][0] = hA; va[p][1] = lA;                                          \
        uint4 hB = make_uint4(0,0,0,0), lB = hB;                               \
        if ((NB & 127) == 0 || (n0 + r_) < NB) {                               \
            hB = *(const uint4*)(Bh + (size_t)(n0 + r_) * KTP + k_);           \
            if (PASSES == 3) lB = *(const uint4*)(Bl + (size_t)(n0 + r_) * KTP + k_); \
        }                                                                      \
        vb[p][0] = hB; vb[p][1] = lB;                                          \
    } } while (0)

#define STORES() do {                                                          \
    _Pragma("unroll")                                                          \
    for (int p = 0; p < 2; p++) {                                              \
        int i_ = tid + p * 256;                                                \
        int r_ = i_ >> 2, v8_ = (i_ & 3) * 8;                                  \
        *(uint4*)&As0[r_ * LDS + v8_] = va[p][0];                              \
        if (PASSES == 3) *(uint4*)&As1[r_ * LDS + v8_] = va[p][1];             \
        *(uint4*)&Bs0[r_ * LDS + v8_] = vb[p][0];                              \
        if (PASSES == 3) *(uint4*)&Bs1[r_ * LDS + v8_] = vb[p][1];             \
    } } while (0)

#define MMASET() do {                                                          \
    _Pragma("unroll")                                                          \
    for (int mi = 0; mi < 4; mi++)                                             \
        _Pragma("unroll")                                                      \
        for (int bj = 0; bj < 2; bj++) {                                       \
            mma16816(C[mi][bj * 2],     Af[mi], &Bf[bj][0]);                   \
            mma16816(C[mi][bj * 2 + 1], Af[mi], &Bf[bj][2]);                   \
        } } while (0)

    LOADG(0);
    STORES();
    __syncthreads();

    for (int c = 0; c < NCH; c++) {
        if (c + 1 < NCH) LOADG(c + 1);
        #pragma unroll
        for (int ks = 0; ks < 2; ks++) {
            uint32_t Af[4][4], Bf[2][4];
            const uint32_t ko = ks * 32;   // 16 halves = 32 bytes
            if (PASSES == 3) {
                #pragma unroll
                for (int mi = 0; mi < 4; mi++) ldsm4(Af[mi], a0b + aoff[mi] + ko);
                #pragma unroll
                for (int bj = 0; bj < 2; bj++) ldsm4(Bf[bj], b1b + boff[bj] + ko);
                MMASET();
                #pragma unroll
                for (int bj = 0; bj < 2; bj++) ldsm4(Bf[bj], b0b + boff[bj] + ko);
                MMASET();
                #pragma unroll
                for (int mi = 0; mi < 4; mi++) ldsm4(Af[mi], a1b + aoff[mi] + ko);
                MMASET();
            } else {
                #pragma unroll
                for (int mi = 0; mi < 4; mi++) ldsm4(Af[mi], a0b + aoff[mi] + ko);
                #pragma unroll
                for (int bj = 0; bj < 2; bj++) ldsm4(Bf[bj], b0b + boff[bj] + ko);
                MMASET();
            }
        }
        __syncthreads();
        if (c + 1 < NCH) { STORES(); __syncthreads(); }
    }

    const int gid = lane >> 2, tig = lane & 3;

    if (EPI <= 2) {
        #pragma unroll
        for (int fi = 0; fi < 4; fi++) {
            int cg = n0 + warp_n + fi * 8 + 2 * tig;
            bool c0ok = (EPI != 2) || (cg < NB);
            bool c1ok = (EPI != 2) || (cg + 1 < NB);
            float bv0 = c0ok ? aux[cg] : 0.f;
            float bv1 = c1ok ? aux[cg + 1] : 0.f;
            #pragma unroll
            for (int mi = 0; mi < 4; mi++) {
                int r0 = m0 + warp_m + mi * 16 + gid;
                float v00 = C[mi][fi][0] + bv0, v01 = C[mi][fi][1] + bv1;
                float v10 = C[mi][fi][2] + bv0, v11 = C[mi][fi][3] + bv1;
                if (RELU) {
                    v00 = fmaxf(v00, 0.f); v01 = fmaxf(v01, 0.f);
                    v10 = fmaxf(v10, 0.f); v11 = fmaxf(v11, 0.f);
                }
                if (EPI == 2) {
                    if (c0ok) { of[(size_t)r0 * OSTR + cg] = v00;
                                of[(size_t)(r0 + 8) * OSTR + cg] = v10; }
                    if (c1ok) { of[(size_t)r0 * OSTR + cg + 1] = v01;
                                of[(size_t)(r0 + 8) * OSTR + cg + 1] = v11; }
                } else {
                    __half h00, h01, h10, h11, l00, l01, l10, l11;
                    h_split(v00, h00, l00); h_split(v01, h01, l01);
                    h_split(v10, h10, l10); h_split(v11, h11, l11);
                    *(__half2*)(oh + (size_t)r0 * OSTR + cg)       = __halves2half2(h00, h01);
                    *(__half2*)(oh + (size_t)(r0 + 8) * OSTR + cg) = __halves2half2(h10, h11);
                    if (EPI == 0) {
                        *(__half2*)(ol + (size_t)r0 * OSTR + cg)       = __halves2half2(l00, l01);
                        *(__half2*)(ol + (size_t)(r0 + 8) * OSTR + cg) = __halves2half2(l10, l11);
                    }
                }
            }
        }
    } else {
        float best[8]; unsigned bk[8];
        #pragma unroll
        for (int i = 0; i < 8; i++) { best[i] = 3.4e38f; bk[i] = 0; }
        #pragma unroll
        for (int fi = 0; fi < 4; fi++) {
            int cg = n0 + warp_n + fi * 8 + 2 * tig;
            float cn0 = aux[cg], cn1 = aux[cg + 1];
            #pragma unroll
            for (int mi = 0; mi < 4; mi++) {
                float d;
                d = cn0 - 2.f * C[mi][fi][0];
                if (d < best[2 * mi]) { best[2 * mi] = d; bk[2 * mi] = (unsigned)cg; }
                d = cn1 - 2.f * C[mi][fi][1];
                if (d < best[2 * mi]) { best[2 * mi] = d; bk[2 * mi] = (unsigned)(cg + 1); }
                d = cn0 - 2.f * C[mi][fi][2];
                if (d < best[2 * mi + 1]) { best[2 * mi + 1] = d; bk[2 * mi + 1] = (unsigned)cg; }
                d = cn1 - 2.f * C[mi][fi][3];
                if (d < best[2 * mi + 1]) { best[2 * mi + 1] = d; bk[2 * mi + 1] = (unsigned)(cg + 1); }
            }
        }
        __syncthreads();
        ull* red = (ull*)As0;
        if (tid < 128) red[tid] = ~0ULL;
        __syncthreads();
        #pragma unroll
        for (int mi = 0; mi < 4; mi++)
            #pragma unroll
            for (int h = 0; h < 2; h++) {
                int rl = warp_m + mi * 16 + gid + 8 * h;
                ull key = ((ull)ford(best[2 * mi + h]) << 32) | (ull)bk[2 * mi + h];
                atomicMin(&red[rl], key);
            }
        __syncthreads();
        if (tid < 128) atomicMin(&keys[m0 + tid], red[tid]);
    }
#undef LOADG
#undef STORES
#undef MMASET
}

// ---------------- launch ----------------------------------------------------
extern "C" void kernel_launch(void* const* d_in, const int* in_sizes, int n_in,
                              void* d_out, int out_size)
{
    const float* mels = (const float*)d_in[0];
    const float* ew1  = (const float*)d_in[1];
    const float* eb1  = (const float*)d_in[2];
    const float* ew2  = (const float*)d_in[3];
    const float* eb2  = (const float*)d_in[4];
    const float* cb   = (const float*)d_in[5];
    const float* dw1  = (const float*)d_in[6];
    const float* db1  = (const float*)d_in[7];
    const float* dw2  = (const float*)d_in[8];
    const float* db2  = (const float*)d_in[9];

    float* out = (float*)d_out;

    __half *mh, *ml, *xh, *xl, *yh, *yl, *wh, *wl, *cbh, *cbl;
    float *cn, *idxd;
    ull *keys;
    cudaGetSymbolAddress((void**)&mh, g_mh);   cudaGetSymbolAddress((void**)&ml, g_ml);
    cudaGetSymbolAddress((void**)&xh, g_xh);   cudaGetSymbolAddress((void**)&xl, g_xl);
    cudaGetSymbolAddress((void**)&yh, g_yh);   cudaGetSymbolAddress((void**)&yl, g_yl);
    cudaGetSymbolAddress((void**)&wh, g_wh);   cudaGetSymbolAddress((void**)&wl, g_wl);
    cudaGetSymbolAddress((void**)&cbh, g_cbh); cudaGetSymbolAddress((void**)&cbl, g_cbl);
    cudaGetSymbolAddress((void**)&cn, g_cn);
    cudaGetSymbolAddress((void**)&keys, g_keys);
    cudaGetSymbolAddress((void**)&idxd, g_idxd);

    float* recon = out;
    float* idx_f = (out_size >= (int)((size_t)ROWS * INV + ROWS))
                     ? out + (size_t)ROWS * INV
                     : idxd;

    // ---- prep ----
    {
        size_t n = (size_t)ROWS * INV;
        split_arr<<<(unsigned)((n + 255) / 256), 256>>>(mels, mh, ml, n);
    }
    prep_w<INV, HV, 256 ><<<(HV * 256  + 255) / 256, 256>>>(ew1, wh + OW1, wl + OW1);
    prep_w<HV,  DV, 1536><<<(DV * 1536 + 255) / 256, 256>>>(ew2, wh + OW2, wl + OW2);
    prep_w<DV,  HV, 1536><<<(HV * 1536 + 255) / 256, 256>>>(dw1, wh + OW3, wl + OW3);
    prep_w<HV,  INV, 1536><<<(INV * 1536 + 255) / 256, 256>>>(dw2, wh + OW4, wl + OW4);
    {
        size_t n = (size_t)KV * DV;
        split_arr<<<(unsigned)((n + 255) / 256), 256>>>(cb, cbh, cbl, n);
    }
    cnorm_kernel<<<KV / 8, 256>>>(cb, cn);
    init_keys<<<ROWS / 256, 256>>>(keys);

    // ---- encoder (3-pass fp16 split == fp32-accurate) ----
    mma_gemm<INV, HV, 240, 1, 3, 0, 1, HV><<<dim3(HV / 128, ROWS / 128), 256>>>(
        mh, ml, wh + OW1, wl + OW1, eb1, xh, xl, nullptr, nullptr);
    mma_gemm<HV, DV, 1536, 1, 3, 0, 0, DV><<<dim3(DV / 128, ROWS / 128), 256>>>(
        xh, xl, wh + OW2, wl + OW2, eb2, yh, yl, nullptr, nullptr);

    // ---- VQ (3-pass split distances, exact argmin) ----
    mma_gemm<DV, KV, 512, 0, 3, 3, 0, 0><<<dim3(KV / 128, ROWS / 128), 256>>>(
        yh, yl, cbh, cbl, cn, nullptr, nullptr, nullptr, keys);
    gather_q<<<ROWS / 128, 256>>>(keys, cbh, xh, idx_f);

    // ---- decoder (1-pass fp16) ----
    mma_gemm<DV, HV, 1536, 1, 1, 1, 1, HV><<<dim3(HV / 128, ROWS / 128), 256>>>(
        xh, nullptr, wh + OW3, nullptr, db1, yh, nullptr, nullptr, nullptr);
    mma_gemm<HV, INV, 1536, 1, 1, 2, 0, INV><<<dim3(1, ROWS / 128), 256>>>(
        yh, nullptr, wh + OW4, nullptr, db2, nullptr, nullptr, recon, nullptr);
}

// round 4
// speedup vs baseline: 5.8579x; 1.0844x over previous
#include <cuda_runtime.h>
#include <cuda_fp16.h>
#include <cstdint>

#define BV   16
#define TV   2048
#define INV  80
#define HV   512
#define DV   512
#define KV   1024
#define ROWS (BV * TV)   // 32768

typedef unsigned long long ull;

// ---------------- scratch (device globals; no allocation allowed) ----------
__device__ __half g_mh[(size_t)ROWS * INV];
__device__ __half g_ml[(size_t)ROWS * INV];
__device__ __half g_xh[(size_t)ROWS * DV];
__device__ __half g_xl[(size_t)ROWS * DV];
__device__ __half g_yh[(size_t)ROWS * DV];
__device__ __half g_yl[(size_t)ROWS * DV];
#define OW1 0
#define OW2 131072
#define OW3 917504
#define OW4 1703936
#define WTOT (1826816 + 128 * 1536)   // pad: dec2 N-tail clamp stays in-bounds
__device__ __half g_wh[WTOT];
__device__ __half g_wl[WTOT];
__device__ __half g_cbh[(size_t)KV * DV];
__device__ __half g_cbl[(size_t)KV * DV];
__device__ float  g_cn[KV];
__device__ ull    g_keys[ROWS];
__device__ float  g_idxd[ROWS];

// ---------------- helpers --------------------------------------------------
__device__ __forceinline__ uint32_t smem_u32(const void* p) {
    uint32_t a;
    asm("{ .reg .u64 t; cvta.to.shared.u64 t, %1; cvt.u32.u64 %0, t; }"
        : "=r"(a) : "l"(p));
    return a;
}
__device__ __forceinline__ void ldsm4(uint32_t* r, uint32_t addr) {
    asm volatile("ldmatrix.sync.aligned.m8n8.x4.shared.b16 {%0,%1,%2,%3}, [%4];"
                 : "=r"(r[0]), "=r"(r[1]), "=r"(r[2]), "=r"(r[3]) : "r"(addr));
}
__device__ __forceinline__ void mma16816(float* c, const uint32_t* a, const uint32_t* b) {
    asm volatile(
        "mma.sync.aligned.m16n8k16.row.col.f32.f16.f16.f32 "
        "{%0,%1,%2,%3}, {%4,%5,%6,%7}, {%8,%9}, {%0,%1,%2,%3};"
        : "+f"(c[0]), "+f"(c[1]), "+f"(c[2]), "+f"(c[3])
        : "r"(a[0]), "r"(a[1]), "r"(a[2]), "r"(a[3]), "r"(b[0]), "r"(b[1]));
}
__device__ __forceinline__ void cp16(uint32_t dst, const void* src, uint32_t sz) {
    asm volatile("cp.async.cg.shared.global [%0], [%1], 16, %2;"
                 :: "r"(dst), "l"(src), "r"(sz));
}
#define CP_COMMIT() asm volatile("cp.async.commit_group;" ::: "memory")
#define CP_WAIT1()  asm volatile("cp.async.wait_group 1;" ::: "memory")

__device__ __forceinline__ unsigned ford(float f) {
    unsigned u = __float_as_uint(f);
    return (u & 0x80000000u) ? ~u : (u | 0x80000000u);
}
__device__ __forceinline__ void h_split(float v, __half& h, __half& l) {
    h = __float2half_rn(v);
    l = __float2half_rn(v - __half2float(h));
}

// ---------------- prep kernels ---------------------------------------------
__global__ void split_arr(const float* __restrict__ x, __half* __restrict__ h,
                          __half* __restrict__ l, size_t n) {
    size_t i = (size_t)blockIdx.x * blockDim.x + threadIdx.x;
    if (i < n) { __half hh, ll; h_split(x[i], hh, ll); h[i] = hh; l[i] = ll; }
}
template<int CIN, int COUT, int KTP>
__global__ void prep_w(const float* __restrict__ w, __half* __restrict__ wh,
                       __half* __restrict__ wl) {
    int i = blockIdx.x * 256 + threadIdx.x;
    if (i >= COUT * KTP) return;
    int co = i / KTP, k = i - co * KTP;
    float v = 0.f;
    if (k < 3 * CIN) {
        int d = k / CIN, ci = k - d * CIN;
        v = w[((size_t)co * CIN + ci) * 3 + d];
    }
    __half hh, ll; h_split(v, hh, ll);
    wh[i] = hh; wl[i] = ll;
}
__global__ void cnorm_init(const float* __restrict__ cb, float* __restrict__ cn,
                           ull* __restrict__ keys) {
    int k = blockIdx.x * 8 + (threadIdx.x >> 5);
    int lane = threadIdx.x & 31;
    float s = 0.f;
    const float* row = cb + (size_t)k * DV;
    for (int c = lane; c < DV; c += 32) { float v = row[c]; s += v * v; }
    #pragma unroll
    for (int o = 16; o; o >>= 1) s += __shfl_xor_sync(0xFFFFFFFFu, s, o);
    if (lane == 0) cn[k] = s;
    int i = blockIdx.x * 256 + threadIdx.x;   // 128 blocks * 256 = 32768
    if (i < ROWS) keys[i] = ~0ULL;
}
__global__ void gather_q(const ull* __restrict__ keys, const __half* __restrict__ cbh,
                         __half* __restrict__ qh, float* __restrict__ idxf) {
    int r0 = blockIdx.x * 128;
    int tid = threadIdx.x;
    if (tid < 128)
        idxf[r0 + tid] = (float)(unsigned)(keys[r0 + tid] & 0xFFFFFFFFu);
    for (int e = tid; e < 128 * DV; e += 256) {
        int r = e >> 9, c = e & 511;
        unsigned k = (unsigned)(keys[r0 + r] & 0xFFFFFFFFu);
        qh[(size_t)(r0 + r) * DV + c] = cbh[(size_t)k * DV + c];
    }
}

// ---------------- mma.sync fp16-split GEMM, 3-stage cp.async pipeline -------
// C[m, n] = sum_k A[m,k] * B[n,k];  A via optional conv im2col (k = d*CIN+ci,
// row shift d-1).  PASSES=3: A0B1 + A0B0 + A1B0 (fp32-accurate split).
// EPI: 0 = bias(+relu) -> split fp16 hi/lo   1 = bias(+relu) -> fp16 hi only
//      2 = bias -> fp32 out (col<NB guard)   3 = VQ argmin (aux = ||c||^2)
template<int CIN, int NB, int KT, int CONV, int PASSES, int EPI, int RELU, int OSTR>
__global__ __launch_bounds__(256)
void mma_gemm(const __half* __restrict__ Ah, const __half* __restrict__ Al,
              const __half* __restrict__ Bh, const __half* __restrict__ Bl,
              const float* __restrict__ aux,
              __half* __restrict__ oh, __half* __restrict__ ol,
              float* __restrict__ of, ull* __restrict__ keys)
{
    constexpr int NCH   = (KT + 31) / 32;
    constexpr int KTP   = NCH * 32;
    constexpr int LDS   = 40;                      // halves per row (80 B)
    constexpr int TILEB = 128 * LDS * 2;           // 10240 B
    constexpr int NT    = (PASSES == 3) ? 4 : 2;   // tiles per stage
    constexpr int STB   = NT * TILEB;
    constexpr int S     = 3;

    extern __shared__ char smem[];
    const uint32_t sb = smem_u32(smem);

    const int tid = threadIdx.x, lane = tid & 31, wid = tid >> 5;
    const int warp_m = (wid & 1) * 64, warp_n = (wid >> 1) * 32;
    const int n0 = blockIdx.x * 128, m0 = blockIdx.y * 128;
    const int bb = CONV ? m0 / TV : 0;
    const int tl = CONV ? m0 % TV : 0;

    float C[4][4][4];
    #pragma unroll
    for (int i = 0; i < 4; i++)
        #pragma unroll
        for (int j = 0; j < 4; j++)
            #pragma unroll
            for (int q = 0; q < 4; q++) C[i][j][q] = 0.f;

    uint32_t aoff[4], boff[2];
    #pragma unroll
    for (int mi = 0; mi < 4; mi++)
        aoff[mi] = ((warp_m + mi * 16 + (lane & 15)) * LDS + (lane >> 4) * 8) * 2;
    #pragma unroll
    for (int bj = 0; bj < 2; bj++)
        boff[bj] = ((warp_n + bj * 16 + ((lane >> 4) << 3) + (lane & 7)) * LDS
                    + ((lane >> 3) & 1) * 8) * 2;

    // issue cp.async loads for chunk cc into stage st
    auto LOADC = [&](int cc, int st) {
        const uint32_t base = sb + (uint32_t)st * STB;
        #pragma unroll
        for (int p = 0; p < 2; p++) {
            int i_ = tid + p * 256;
            int r_ = i_ >> 2, v8 = (i_ & 3) * 8;
            uint32_t doff = (uint32_t)(r_ * LDS + v8) * 2;
            // ---- A (im2col) ----
            {
                int k_ = cc * 32 + v8;
                int d_  = CONV ? k_ / CIN : 0;
                int ci_ = k_ - d_ * CIN;
                bool ok = (KT == KTP) || (k_ < KT);
                size_t row_;
                if (CONV) {
                    int t_ = tl + r_ + d_ - 1;
                    bool tin = (t_ >= 0 && t_ < TV);
                    ok = ok && tin;
                    row_ = (size_t)bb * TV + (tin ? t_ : 0);
                } else {
                    row_ = (size_t)(m0 + r_);
                }
                if (!ok) ci_ = 0;
                uint32_t sz = ok ? 16u : 0u;
                const size_t go = row_ * CIN + ci_;
                cp16(base + doff, Ah + go, sz);
                if (PASSES == 3) cp16(base + TILEB + doff, Al + go, sz);
            }
            // ---- B ----
            {
                int k_ = cc * 32 + v8;
                bool ok = ((NB & 127) == 0) || ((n0 + r_) < NB);
                int rb = ok ? (n0 + r_) : 0;
                uint32_t sz = ok ? 16u : 0u;
                const size_t go = (size_t)rb * KTP + k_;
                const uint32_t bbase = base + (PASSES == 3 ? 2 : 1) * TILEB;
                cp16(bbase + doff, Bh + go, sz);
                if (PASSES == 3) cp16(bbase + TILEB + doff, Bl + go, sz);
            }
        }
    };

#define MMASET() do {                                                          \
    _Pragma("unroll")                                                          \
    for (int mi = 0; mi < 4; mi++)                                             \
        _Pragma("unroll")                                                      \
        for (int bj = 0; bj < 2; bj++) {                                       \
            mma16816(C[mi][bj * 2],     Af[mi], &Bf[bj][0]);                   \
            mma16816(C[mi][bj * 2 + 1], Af[mi], &Bf[bj][2]);                   \
        } } while (0)

    // prologue: stages 0,1
    LOADC(0, 0); CP_COMMIT();
    LOADC(1, 1); CP_COMMIT();

    for (int c = 0; c < NCH; c++) {
        CP_WAIT1();
        __syncthreads();
        const int st = c % S;
        const uint32_t a0b = sb + (uint32_t)st * STB;
        const uint32_t a1b = a0b + TILEB;
        const uint32_t b0b = a0b + (PASSES == 3 ? 2 : 1) * TILEB;
        const uint32_t b1b = b0b + TILEB;

        #pragma unroll
        for (int ks = 0; ks < 2; ks++) {
            uint32_t Af[4][4], Bf[2][4];
            const uint32_t ko = ks * 32;          // 16 halves = 32 B
            if (PASSES == 3) {
                #pragma unroll
                for (int mi = 0; mi < 4; mi++) ldsm4(Af[mi], a0b + aoff[mi] + ko);
                #pragma unroll
                for (int bj = 0; bj < 2; bj++) ldsm4(Bf[bj], b1b + boff[bj] + ko);
                MMASET();
                #pragma unroll
                for (int bj = 0; bj < 2; bj++) ldsm4(Bf[bj], b0b + boff[bj] + ko);
                MMASET();
                #pragma unroll
                for (int mi = 0; mi < 4; mi++) ldsm4(Af[mi], a1b + aoff[mi] + ko);
                MMASET();
            } else {
                #pragma unroll
                for (int mi = 0; mi < 4; mi++) ldsm4(Af[mi], a0b + aoff[mi] + ko);
                #pragma unroll
                for (int bj = 0; bj < 2; bj++) ldsm4(Bf[bj], b0b + boff[bj] + ko);
                MMASET();
            }
        }
        // issue loads for chunk c+2 (stage (c+2)%3 held chunk c-1: done)
        const int nc = c + S - 1;
        if (nc < NCH) LOADC(nc, nc % S);
        CP_COMMIT();                              // empty group at tail keeps
    }                                             // wait_group accounting valid

    const int gid = lane >> 2, tig = lane & 3;

    if (EPI <= 2) {
        #pragma unroll
        for (int fi = 0; fi < 4; fi++) {
            int cg = n0 + warp_n + fi * 8 + 2 * tig;
            bool c0ok = (EPI != 2) || (cg < NB);
            bool c1ok = (EPI != 2) || (cg + 1 < NB);
            float bv0 = c0ok ? aux[cg] : 0.f;
            float bv1 = c1ok ? aux[cg + 1] : 0.f;
            #pragma unroll
            for (int mi = 0; mi < 4; mi++) {
                int r0 = m0 + warp_m + mi * 16 + gid;
                float v00 = C[mi][fi][0] + bv0, v01 = C[mi][fi][1] + bv1;
                float v10 = C[mi][fi][2] + bv0, v11 = C[mi][fi][3] + bv1;
                if (RELU) {
                    v00 = fmaxf(v00, 0.f); v01 = fmaxf(v01, 0.f);
                    v10 = fmaxf(v10, 0.f); v11 = fmaxf(v11, 0.f);
                }
                if (EPI == 2) {
                    if (c0ok) { of[(size_t)r0 * OSTR + cg] = v00;
                                of[(size_t)(r0 + 8) * OSTR + cg] = v10; }
                    if (c1ok) { of[(size_t)r0 * OSTR + cg + 1] = v01;
                                of[(size_t)(r0 + 8) * OSTR + cg + 1] = v11; }
                } else {
                    __half h00, h01, h10, h11, l00, l01, l10, l11;
                    h_split(v00, h00, l00); h_split(v01, h01, l01);
                    h_split(v10, h10, l10); h_split(v11, h11, l11);
                    *(__half2*)(oh + (size_t)r0 * OSTR + cg)       = __halves2half2(h00, h01);
                    *(__half2*)(oh + (size_t)(r0 + 8) * OSTR + cg) = __halves2half2(h10, h11);
                    if (EPI == 0) {
                        *(__half2*)(ol + (size_t)r0 * OSTR + cg)       = __halves2half2(l00, l01);
                        *(__half2*)(ol + (size_t)(r0 + 8) * OSTR + cg) = __halves2half2(l10, l11);
                    }
                }
            }
        }
    } else {
        float best[8]; unsigned bk[8];
        #pragma unroll
        for (int i = 0; i < 8; i++) { best[i] = 3.4e38f; bk[i] = 0; }
        #pragma unroll
        for (int fi = 0; fi < 4; fi++) {
            int cg = n0 + warp_n + fi * 8 + 2 * tig;
            float cn0 = aux[cg], cn1 = aux[cg + 1];
            #pragma unroll
            for (int mi = 0; mi < 4; mi++) {
                float d;
                d = cn0 - 2.f * C[mi][fi][0];
                if (d < best[2 * mi]) { best[2 * mi] = d; bk[2 * mi] = (unsigned)cg; }
                d = cn1 - 2.f * C[mi][fi][1];
                if (d < best[2 * mi]) { best[2 * mi] = d; bk[2 * mi] = (unsigned)(cg + 1); }
                d = cn0 - 2.f * C[mi][fi][2];
                if (d < best[2 * mi + 1]) { best[2 * mi + 1] = d; bk[2 * mi + 1] = (unsigned)cg; }
                d = cn1 - 2.f * C[mi][fi][3];
                if (d < best[2 * mi + 1]) { best[2 * mi + 1] = d; bk[2 * mi + 1] = (unsigned)(cg + 1); }
            }
        }
        __syncthreads();
        ull* red = (ull*)smem;
        if (tid < 128) red[tid] = ~0ULL;
        __syncthreads();
        #pragma unroll
        for (int mi = 0; mi < 4; mi++)
            #pragma unroll
            for (int h = 0; h < 2; h++) {
                int rl = warp_m + mi * 16 + gid + 8 * h;
                ull key = ((ull)ford(best[2 * mi + h]) << 32) | (ull)bk[2 * mi + h];
                atomicMin(&red[rl], key);
            }
        __syncthreads();
        if (tid < 128) atomicMin(&keys[m0 + tid], red[tid]);
    }
#undef MMASET
}

// ---------------- launch ----------------------------------------------------
extern "C" void kernel_launch(void* const* d_in, const int* in_sizes, int n_in,
                              void* d_out, int out_size)
{
    const float* mels = (const float*)d_in[0];
    const float* ew1  = (const float*)d_in[1];
    const float* eb1  = (const float*)d_in[2];
    const float* ew2  = (const float*)d_in[3];
    const float* eb2  = (const float*)d_in[4];
    const float* cb   = (const float*)d_in[5];
    const float* dw1  = (const float*)d_in[6];
    const float* db1  = (const float*)d_in[7];
    const float* dw2  = (const float*)d_in[8];
    const float* db2  = (const float*)d_in[9];

    float* out = (float*)d_out;

    __half *mh, *ml, *xh, *xl, *yh, *yl, *wh, *wl, *cbh, *cbl;
    float *cn, *idxd;
    ull *keys;
    cudaGetSymbolAddress((void**)&mh, g_mh);   cudaGetSymbolAddress((void**)&ml, g_ml);
    cudaGetSymbolAddress((void**)&xh, g_xh);   cudaGetSymbolAddress((void**)&xl, g_xl);
    cudaGetSymbolAddress((void**)&yh, g_yh);   cudaGetSymbolAddress((void**)&yl, g_yl);
    cudaGetSymbolAddress((void**)&wh, g_wh);   cudaGetSymbolAddress((void**)&wl, g_wl);
    cudaGetSymbolAddress((void**)&cbh, g_cbh); cudaGetSymbolAddress((void**)&cbl, g_cbl);
    cudaGetSymbolAddress((void**)&cn, g_cn);
    cudaGetSymbolAddress((void**)&keys, g_keys);
    cudaGetSymbolAddress((void**)&idxd, g_idxd);

    float* recon = out;
    float* idx_f = (out_size >= (int)((size_t)ROWS * INV + ROWS))
                     ? out + (size_t)ROWS * INV
                     : idxd;

    constexpr int SM3 = 3 * 4 * 128 * 40 * 2;   // 122880
    constexpr int SM1 = 3 * 2 * 128 * 40 * 2;   //  61440
    static bool attr_done = false;
    if (!attr_done) {
        cudaFuncSetAttribute(mma_gemm<INV, HV, 240, 1, 3, 0, 1, HV>,
                             cudaFuncAttributeMaxDynamicSharedMemorySize, SM3);
        cudaFuncSetAttribute(mma_gemm<HV, DV, 1536, 1, 3, 0, 0, DV>,
                             cudaFuncAttributeMaxDynamicSharedMemorySize, SM3);
        cudaFuncSetAttribute(mma_gemm<DV, KV, 512, 0, 3, 3, 0, 0>,
                             cudaFuncAttributeMaxDynamicSharedMemorySize, SM3);
        cudaFuncSetAttribute(mma_gemm<DV, HV, 1536, 1, 1, 1, 1, HV>,
                             cudaFuncAttributeMaxDynamicSharedMemorySize, SM1);
        cudaFuncSetAttribute(mma_gemm<HV, INV, 1536, 1, 1, 2, 0, INV>,
                             cudaFuncAttributeMaxDynamicSharedMemorySize, SM1);
        attr_done = true;
    }

    // ---- prep ----
    {
        size_t n = (size_t)ROWS * INV;
        split_arr<<<(unsigned)((n + 255) / 256), 256>>>(mels, mh, ml, n);
    }
    prep_w<INV, HV, 256  ><<<(HV * 256  + 255) / 256, 256>>>(ew1, wh + OW1, wl + OW1);
    prep_w<HV,  DV, 1536 ><<<(DV * 1536 + 255) / 256, 256>>>(ew2, wh + OW2, wl + OW2);
    prep_w<DV,  HV, 1536 ><<<(HV * 1536 + 255) / 256, 256>>>(dw1, wh + OW3, wl + OW3);
    prep_w<HV,  INV, 1536><<<(INV * 1536 + 255) / 256, 256>>>(dw2, wh + OW4, wl + OW4);
    {
        size_t n = (size_t)KV * DV;
        split_arr<<<(unsigned)((n + 255) / 256), 256>>>(cb, cbh, cbl, n);
    }
    cnorm_init<<<KV / 8, 256>>>(cb, cn, keys);

    // ---- encoder (3-pass fp16 split == fp32-accurate) ----
    mma_gemm<INV, HV, 240, 1, 3, 0, 1, HV><<<dim3(HV / 128, ROWS / 128), 256, SM3>>>(
        mh, ml, wh + OW1, wl + OW1, eb1, xh, xl, nullptr, nullptr);
    mma_gemm<HV, DV, 1536, 1, 3, 0, 0, DV><<<dim3(DV / 128, ROWS / 128), 256, SM3>>>(
        xh, xl, wh + OW2, wl + OW2, eb2, yh, yl, nullptr, nullptr);

    // ---- VQ (3-pass split distances, exact argmin) ----
    mma_gemm<DV, KV, 512, 0, 3, 3, 0, 0><<<dim3(KV / 128, ROWS / 128), 256, SM3>>>(
        yh, yl, cbh, cbl, cn, nullptr, nullptr, nullptr, keys);
    gather_q<<<ROWS / 128, 256>>>(keys, cbh, xh, idx_f);

    // ---- decoder (1-pass fp16) ----
    mma_gemm<DV, HV, 1536, 1, 1, 1, 1, HV><<<dim3(HV / 128, ROWS / 128), 256, SM1>>>(
        xh, nullptr, wh + OW3, nullptr, db1, yh, nullptr, nullptr, nullptr);
    mma_gemm<HV, INV, 1536, 1, 1, 2, 0, INV><<<dim3(1, ROWS / 128), 256, SM1>>>(
        yh, nullptr, wh + OW4, nullptr, db2, nullptr, nullptr, recon, nullptr);
}

// round 7
// speedup vs baseline: 5.8928x; 1.0060x over previous
#include <cuda_runtime.h>
#include <cuda_fp16.h>
#include <cstdint>

#define BV   16
#define TV   2048
#define INV  80
#define HV   512
#define DV   512
#define KV   1024
#define ROWS (BV * TV)   // 32768

typedef unsigned long long ull;

// ---------------- scratch (device globals; no allocation allowed) ----------
__device__ __half g_mh[(size_t)ROWS * INV];
__device__ __half g_ml[(size_t)ROWS * INV];
__device__ __half g_xh[(size_t)ROWS * DV];
__device__ __half g_xl[(size_t)ROWS * DV];
__device__ __half g_yh[(size_t)ROWS * DV];
__device__ __half g_yl[(size_t)ROWS * DV];
#define OW1 0
#define OW2 131072
#define OW3 917504
#define OW4 1703936
#define WTOT (1826816 + 128 * 1536)   // pad: dec2 N-tail clamp stays in-bounds
__device__ __half g_wh[WTOT];
__device__ __half g_wl[WTOT];
__device__ __half g_cbh[(size_t)KV * DV];
__device__ __half g_cbl[(size_t)KV * DV];
__device__ float  g_cn[KV];
__device__ ull    g_keys[ROWS];
__device__ float  g_idxd[ROWS];

// ---------------- helpers --------------------------------------------------
__device__ __forceinline__ uint32_t smem_u32(const void* p) {
    uint32_t a;
    asm("{ .reg .u64 t; cvta.to.shared.u64 t, %1; cvt.u32.u64 %0, t; }"
        : "=r"(a) : "l"(p));
    return a;
}
__device__ __forceinline__ void ldsm4(uint32_t* r, uint32_t addr) {
    asm volatile("ldmatrix.sync.aligned.m8n8.x4.shared.b16 {%0,%1,%2,%3}, [%4];"
                 : "=r"(r[0]), "=r"(r[1]), "=r"(r[2]), "=r"(r[3]) : "r"(addr));
}
__device__ __forceinline__ void mma16816(float* c, const uint32_t* a, const uint32_t* b) {
    asm volatile(
        "mma.sync.aligned.m16n8k16.row.col.f32.f16.f16.f32 "
        "{%0,%1,%2,%3}, {%4,%5,%6,%7}, {%8,%9}, {%0,%1,%2,%3};"
        : "+f"(c[0]), "+f"(c[1]), "+f"(c[2]), "+f"(c[3])
        : "r"(a[0]), "r"(a[1]), "r"(a[2]), "r"(a[3]), "r"(b[0]), "r"(b[1]));
}
__device__ __forceinline__ void cp16(uint32_t dst, const void* src, uint32_t sz) {
    asm volatile("cp.async.cg.shared.global [%0], [%1], 16, %2;"
                 :: "r"(dst), "l"(src), "r"(sz));
}
#define CP_COMMIT() asm volatile("cp.async.commit_group;" ::: "memory")
#define CP_WAIT1()  asm volatile("cp.async.wait_group 1;" ::: "memory")

__device__ __forceinline__ unsigned ford(float f) {
    unsigned u = __float_as_uint(f);
    return (u & 0x80000000u) ? ~u : (u | 0x80000000u);
}
__device__ __forceinline__ void h_split(float v, __half& h, __half& l) {
    h = __float2half_rn(v);
    l = __float2half_rn(v - __half2float(h));
}

// ---------------- prep kernels ---------------------------------------------
__global__ void split_arr(const float* __restrict__ x, __half* __restrict__ h,
                          __half* __restrict__ l, size_t n) {
    size_t i = (size_t)blockIdx.x * blockDim.x + threadIdx.x;
    if (i < n) { __half hh, ll; h_split(x[i], hh, ll); h[i] = hh; l[i] = ll; }
}
template<int CIN, int COUT, int KTP>
__global__ void prep_w(const float* __restrict__ w, __half* __restrict__ wh,
                       __half* __restrict__ wl) {
    int i = blockIdx.x * 256 + threadIdx.x;
    if (i >= COUT * KTP) return;
    int co = i / KTP, k = i - co * KTP;
    float v = 0.f;
    if (k < 3 * CIN) {
        int d = k / CIN, ci = k - d * CIN;
        v = w[((size_t)co * CIN + ci) * 3 + d];
    }
    __half hh, ll; h_split(v, hh, ll);
    wh[i] = hh; wl[i] = ll;
}
__global__ void cnorm_init(const float* __restrict__ cb, float* __restrict__ cn,
                           ull* __restrict__ keys) {
    int k = blockIdx.x * 8 + (threadIdx.x >> 5);
    int lane = threadIdx.x & 31;
    float s = 0.f;
    const float* row = cb + (size_t)k * DV;
    for (int c = lane; c < DV; c += 32) { float v = row[c]; s += v * v; }
    #pragma unroll
    for (int o = 16; o; o >>= 1) s += __shfl_xor_sync(0xFFFFFFFFu, s, o);
    if (lane == 0) cn[k] = s;
    int i = blockIdx.x * 256 + threadIdx.x;   // 128 blocks * 256 = 32768
    if (i < ROWS) keys[i] = ~0ULL;
}
__global__ void gather_q(const ull* __restrict__ keys, const __half* __restrict__ cbh,
                         __half* __restrict__ qh, float* __restrict__ idxf) {
    int r0 = blockIdx.x * 128;
    int tid = threadIdx.x;
    if (tid < 128)
        idxf[r0 + tid] = (float)(unsigned)(keys[r0 + tid] & 0xFFFFFFFFu);
    for (int e = tid; e < 128 * DV; e += 256) {
        int r = e >> 9, c = e & 511;
        unsigned k = (unsigned)(keys[r0 + r] & 0xFFFFFFFFu);
        qh[(size_t)(r0 + r) * DV + c] = cbh[(size_t)k * DV + c];
    }
}

// ---------------- mma.sync fp16-split GEMM, 3-stage cp.async ----------------
// CTA tile 128 x NTILE (NTILE 256: warp 64x64, NTILE 128: warp 64x32).
// C[m, n] = sum_k A[m,k] * B[n,k];  A via optional conv im2col (k = d*CIN+ci,
// row shift d-1).  PASSES=3: A0B1 + A0B0 + A1B0 (fp32-accurate split).
// EPI: 0 = bias(+relu) -> split fp16 hi/lo   1 = bias(+relu) -> fp16 hi only
//      2 = bias -> fp32 out (col<NB guard)   3 = VQ argmin (aux = ||c||^2)
template<int CIN, int NB, int KT, int CONV, int PASSES, int EPI, int RELU,
         int OSTR, int NTILE>
__global__ __launch_bounds__(256, 1)
void mma_gemm(const __half* __restrict__ Ah, const __half* __restrict__ Al,
              const __half* __restrict__ Bh, const __half* __restrict__ Bl,
              const float* __restrict__ aux,
              __half* __restrict__ oh, __half* __restrict__ ol,
              float* __restrict__ of, ull* __restrict__ keys)
{
    constexpr int NCH    = (KT + 31) / 32;
    constexpr int KTP    = NCH * 32;
    constexpr int LDS    = 40;                        // halves per row (80 B)
    constexpr int ATILEB = 128 * LDS * 2;             // 10240 B
    constexpr int BTILEB = NTILE * LDS * 2;
    constexpr int STB    = (PASSES == 3) ? 2 * (ATILEB + BTILEB) : (ATILEB + BTILEB);
    constexpr int S      = 3;
    constexpr int WNF    = NTILE / 64;                // B 16-col frags per warp
    constexpr int NF     = 2 * WNF;                   // n8 frags per warp

    extern __shared__ char smem[];
    const uint32_t sb = smem_u32(smem);

    const int tid = threadIdx.x, lane = tid & 31, wid = tid >> 5;
    const int warp_m = (wid & 1) * 64;
    const int warp_n = (wid >> 1) * (16 * WNF);
    const int n0 = blockIdx.x * NTILE, m0 = blockIdx.y * 128;
    const int bb = CONV ? m0 / TV : 0;
    const int tl = CONV ? m0 % TV : 0;

    float C[4][NF][4];
    #pragma unroll
    for (int i = 0; i < 4; i++)
        #pragma unroll
        for (int j = 0; j < NF; j++)
            #pragma unroll
            for (int q = 0; q < 4; q++) C[i][j][q] = 0.f;

    uint32_t aoff[4], boff[WNF];
    #pragma unroll
    for (int mi = 0; mi < 4; mi++)
        aoff[mi] = ((warp_m + mi * 16 + (lane & 15)) * LDS + (lane >> 4) * 8) * 2;
    #pragma unroll
    for (int bj = 0; bj < WNF; bj++)
        boff[bj] = ((warp_n + bj * 16 + ((lane >> 4) << 3) + (lane & 7)) * LDS
                    + ((lane >> 3) & 1) * 8) * 2;

    // issue cp.async loads for chunk cc into stage st
    auto LOADC = [&](int cc, int st) {
        const uint32_t base = sb + (uint32_t)st * STB;
        // ---- A (im2col): 128 rows x 4 vec8 ----
        #pragma unroll
        for (int p = 0; p < 2; p++) {
            int i_ = tid + p * 256;
            int r_ = i_ >> 2, v8 = (i_ & 3) * 8;
            uint32_t doff = (uint32_t)(r_ * LDS + v8) * 2;
            int k_ = cc * 32 + v8;
            int d_  = CONV ? k_ / CIN : 0;
            int ci_ = k_ - d_ * CIN;
            bool ok = (KT == KTP) || (k_ < KT);
            size_t row_;
            if (CONV) {
                int t_ = tl + r_ + d_ - 1;
                bool tin = (t_ >= 0 && t_ < TV);
                ok = ok && tin;
                row_ = (size_t)bb * TV + (tin ? t_ : 0);
            } else {
                row_ = (size_t)(m0 + r_);
            }
            if (!ok) ci_ = 0;
            uint32_t sz = ok ? 16u : 0u;
            const size_t go = row_ * CIN + ci_;
            cp16(base + doff, Ah + go, sz);
            if (PASSES == 3) cp16(base + ATILEB + doff, Al + go, sz);
        }
        // ---- B: NTILE rows x 4 vec8 ----
        const uint32_t bbase = base + (PASSES == 3 ? 2 : 1) * ATILEB;
        #pragma unroll
        for (int p = 0; p < NTILE / 64; p++) {
            int i_ = tid + p * 256;
            int r_ = i_ >> 2, v8 = (i_ & 3) * 8;
            uint32_t doff = (uint32_t)(r_ * LDS + v8) * 2;
            int k_ = cc * 32 + v8;
            bool ok = ((NB % NTILE) == 0) || ((n0 + r_) < NB);
            int rb = ok ? (n0 + r_) : 0;
            uint32_t sz = ok ? 16u : 0u;
            const size_t go = (size_t)rb * KTP + k_;
            cp16(bbase + doff, Bh + go, sz);
            if (PASSES == 3) cp16(bbase + BTILEB + doff, Bl + go, sz);
        }
    };

#define MMASET() do {                                                          \
    _Pragma("unroll")                                                          \
    for (int mi = 0; mi < 4; mi++)                                             \
        _Pragma("unroll")                                                      \
        for (int bj = 0; bj < WNF; bj++) {                                     \
            mma16816(C[mi][bj * 2],     Af[mi], &Bf[bj][0]);                   \
            mma16816(C[mi][bj * 2 + 1], Af[mi], &Bf[bj][2]);                   \
        } } while (0)

    // prologue: stages 0,1
    LOADC(0, 0); CP_COMMIT();
    LOADC(1, 1); CP_COMMIT();

    for (int c = 0; c < NCH; c++) {
        CP_WAIT1();
        __syncthreads();
        const int st = c % S;
        const uint32_t a0b = sb + (uint32_t)st * STB;
        const uint32_t a1b = a0b + ATILEB;
        const uint32_t b0b = a0b + (PASSES == 3 ? 2 : 1) * ATILEB;
        const uint32_t b1b = b0b + BTILEB;

        #pragma unroll
        for (int ks = 0; ks < 2; ks++) {
            uint32_t Af[4][4], Bf[WNF][4];
            const uint32_t ko = ks * 32;          // 16 halves = 32 B
            if (PASSES == 3) {
                #pragma unroll
                for (int mi = 0; mi < 4; mi++) ldsm4(Af[mi], a0b + aoff[mi] + ko);
                #pragma unroll
                for (int bj = 0; bj < WNF; bj++) ldsm4(Bf[bj], b1b + boff[bj] + ko);
                MMASET();
                #pragma unroll
                for (int bj = 0; bj < WNF; bj++) ldsm4(Bf[bj], b0b + boff[bj] + ko);
                MMASET();
                #pragma unroll
                for (int mi = 0; mi < 4; mi++) ldsm4(Af[mi], a1b + aoff[mi] + ko);
                MMASET();
            } else {
                #pragma unroll
                for (int mi = 0; mi < 4; mi++) ldsm4(Af[mi], a0b + aoff[mi] + ko);
                #pragma unroll
                for (int bj = 0; bj < WNF; bj++) ldsm4(Bf[bj], b0b + boff[bj] + ko);
                MMASET();
            }
        }
        // issue loads for chunk c+2 (its stage held chunk c-1: done by the
        // __syncthreads() at the top of this iteration)
        const int nc = c + S - 1;
        if (nc < NCH) LOADC(nc, nc % S);
        CP_COMMIT();                              // empty group at tail keeps
    }                                             // wait_group accounting valid

    const int gid = lane >> 2, tig = lane & 3;

    if (EPI <= 2) {
        #pragma unroll
        for (int fi = 0; fi < NF; fi++) {
            int cg = n0 + warp_n + fi * 8 + 2 * tig;
            bool c0ok = (EPI != 2) || (cg < NB);
            bool c1ok = (EPI != 2) || (cg + 1 < NB);
            float bv0 = c0ok ? aux[cg] : 0.f;
            float bv1 = c1ok ? aux[cg + 1] : 0.f;
            #pragma unroll
            for (int mi = 0; mi < 4; mi++) {
                int r0 = m0 + warp_m + mi * 16 + gid;
                float v00 = C[mi][fi][0] + bv0, v01 = C[mi][fi][1] + bv1;
                float v10 = C[mi][fi][2] + bv0, v11 = C[mi][fi][3] + bv1;
                if (RELU) {
                    v00 = fmaxf(v00, 0.f); v01 = fmaxf(v01, 0.f);
                    v10 = fmaxf(v10, 0.f); v11 = fmaxf(v11, 0.f);
                }
                if (EPI == 2) {
                    if (c0ok) { of[(size_t)r0 * OSTR + cg] = v00;
                                of[(size_t)(r0 + 8) * OSTR + cg] = v10; }
                    if (c1ok) { of[(size_t)r0 * OSTR + cg + 1] = v01;
                                of[(size_t)(r0 + 8) * OSTR + cg + 1] = v11; }
                } else {
                    __half h00, h01, h10, h11, l00, l01, l10, l11;
                    h_split(v00, h00, l00); h_split(v01, h01, l01);
                    h_split(v10, h10, l10); h_split(v11, h11, l11);
                    *(__half2*)(oh + (size_t)r0 * OSTR + cg)       = __halves2half2(h00, h01);
                    *(__half2*)(oh + (size_t)(r0 + 8) * OSTR + cg) = __halves2half2(h10, h11);
                    if (EPI == 0) {
                        *(__half2*)(ol + (size_t)r0 * OSTR + cg)       = __halves2half2(l00, l01);
                        *(__half2*)(ol + (size_t)(r0 + 8) * OSTR + cg) = __halves2half2(l10, l11);
                    }
                }
            }
        }
    } else {
        float best[8]; unsigned bk[8];
        #pragma unroll
        for (int i = 0; i < 8; i++) { best[i] = 3.4e38f; bk[i] = 0; }
        #pragma unroll
        for (int fi = 0; fi < NF; fi++) {
            int cg = n0 + warp_n + fi * 8 + 2 * tig;
            float cn0 = aux[cg], cn1 = aux[cg + 1];
            #pragma unroll
            for (int mi = 0; mi < 4; mi++) {
                float d;
                d = cn0 - 2.f * C[mi][fi][0];
                if (d < best[2 * mi]) { best[2 * mi] = d; bk[2 * mi] = (unsigned)cg; }
                d = cn1 - 2.f * C[mi][fi][1];
                if (d < best[2 * mi]) { best[2 * mi] = d; bk[2 * mi] = (unsigned)(cg + 1); }
                d = cn0 - 2.f * C[mi][fi][2];
                if (d < best[2 * mi + 1]) { best[2 * mi + 1] = d; bk[2 * mi + 1] = (unsigned)cg; }
                d = cn1 - 2.f * C[mi][fi][3];
                if (d < best[2 * mi + 1]) { best[2 * mi + 1] = d; bk[2 * mi + 1] = (unsigned)(cg + 1); }
            }
        }
        __syncthreads();
        ull* red = (ull*)smem;
        if (tid < 128) red[tid] = ~0ULL;
        __syncthreads();
        #pragma unroll
        for (int mi = 0; mi < 4; mi++)
            #pragma unroll
            for (int h = 0; h < 2; h++) {
                int rl = warp_m + mi * 16 + gid + 8 * h;
                ull key = ((ull)ford(best[2 * mi + h]) << 32) | (ull)bk[2 * mi + h];
                atomicMin(&red[rl], key);
            }
        __syncthreads();
        if (tid < 128) atomicMin(&keys[m0 + tid], red[tid]);
    }
#undef MMASET
}

// ---------------- launch ----------------------------------------------------
extern "C" void kernel_launch(void* const* d_in, const int* in_sizes, int n_in,
                              void* d_out, int out_size)
{
    const float* mels = (const float*)d_in[0];
    const float* ew1  = (const float*)d_in[1];
    const float* eb1  = (const float*)d_in[2];
    const float* ew2  = (const float*)d_in[3];
    const float* eb2  = (const float*)d_in[4];
    const float* cb   = (const float*)d_in[5];
    const float* dw1  = (const float*)d_in[6];
    const float* db1  = (const float*)d_in[7];
    const float* dw2  = (const float*)d_in[8];
    const float* db2  = (const float*)d_in[9];

    float* out = (float*)d_out;

    __half *mh, *ml, *xh, *xl, *yh, *yl, *wh, *wl, *cbh, *cbl;
    float *cn, *idxd;
    ull *keys;
    cudaGetSymbolAddress((void**)&mh, g_mh);   cudaGetSymbolAddress((void**)&ml, g_ml);
    cudaGetSymbolAddress((void**)&xh, g_xh);   cudaGetSymbolAddress((void**)&xl, g_xl);
    cudaGetSymbolAddress((void**)&yh, g_yh);   cudaGetSymbolAddress((void**)&yl, g_yl);
    cudaGetSymbolAddress((void**)&wh, g_wh);   cudaGetSymbolAddress((void**)&wl, g_wl);
    cudaGetSymbolAddress((void**)&cbh, g_cbh); cudaGetSymbolAddress((void**)&cbl, g_cbl);
    cudaGetSymbolAddress((void**)&cn, g_cn);
    cudaGetSymbolAddress((void**)&keys, g_keys);
    cudaGetSymbolAddress((void**)&idxd, g_idxd);

    float* recon = out;
    float* idx_f = (out_size >= (int)((size_t)ROWS * INV + ROWS))
                     ? out + (size_t)ROWS * INV
                     : idxd;

    // stage bytes: 3-pass/256: 2*(10240+20480)=61440; 1-pass/256: 30720;
    // 1-pass/128: 20480.  x3 stages.
    constexpr int SM3_256 = 3 * 61440;   // 184320
    constexpr int SM1_256 = 3 * 30720;   //  92160
    constexpr int SM1_128 = 3 * 20480;   //  61440
    static bool attr_done = false;
    if (!attr_done) {
        cudaFuncSetAttribute(mma_gemm<INV, HV, 240, 1, 3, 0, 1, HV, 256>,
                             cudaFuncAttributeMaxDynamicSharedMemorySize, SM3_256);
        cudaFuncSetAttribute(mma_gemm<HV, DV, 1536, 1, 3, 0, 0, DV, 256>,
                             cudaFuncAttributeMaxDynamicSharedMemorySize, SM3_256);
        cudaFuncSetAttribute(mma_gemm<DV, KV, 512, 0, 3, 3, 0, 0, 256>,
                             cudaFuncAttributeMaxDynamicSharedMemorySize, SM3_256);
        cudaFuncSetAttribute(mma_gemm<DV, HV, 1536, 1, 1, 1, 1, HV, 256>,
                             cudaFuncAttributeMaxDynamicSharedMemorySize, SM1_256);
        cudaFuncSetAttribute(mma_gemm<HV, INV, 1536, 1, 1, 2, 0, INV, 128>,
                             cudaFuncAttributeMaxDynamicSharedMemorySize, SM1_128);
        attr_done = true;
    }

    // ---- prep ----
    {
        size_t n = (size_t)ROWS * INV;
        split_arr<<<(unsigned)((n + 255) / 256), 256>>>(mels, mh, ml, n);
    }
    prep_w<INV, HV, 256  ><<<(HV * 256  + 255) / 256, 256>>>(ew1, wh + OW1, wl + OW1);
    prep_w<HV,  DV, 1536 ><<<(DV * 1536 + 255) / 256, 256>>>(ew2, wh + OW2, wl + OW2);
    prep_w<DV,  HV, 1536 ><<<(HV * 1536 + 255) / 256, 256>>>(dw1, wh + OW3, wl + OW3);
    prep_w<HV,  INV, 1536><<<(INV * 1536 + 255) / 256, 256>>>(dw2, wh + OW4, wl + OW4);
    {
        size_t n = (size_t)KV * DV;
        split_arr<<<(unsigned)((n + 255) / 256), 256>>>(cb, cbh, cbl, n);
    }
    cnorm_init<<<KV / 8, 256>>>(cb, cn, keys);

    // ---- encoder (3-pass fp16 split == fp32-accurate) ----
    mma_gemm<INV, HV, 240, 1, 3, 0, 1, HV, 256>
        <<<dim3(HV / 256, ROWS / 128), 256, SM3_256>>>(
        mh, ml, wh + OW1, wl + OW1, eb1, xh, xl, nullptr, nullptr);
    mma_gemm<HV, DV, 1536, 1, 3, 0, 0, DV, 256>
        <<<dim3(DV / 256, ROWS / 128), 256, SM3_256>>>(
        xh, xl, wh + OW2, wl + OW2, eb2, yh, yl, nullptr, nullptr);

    // ---- VQ (3-pass split distances, exact argmin) ----
    mma_gemm<DV, KV, 512, 0, 3, 3, 0, 0, 256>
        <<<dim3(KV / 256, ROWS / 128), 256, SM3_256>>>(
        yh, yl, cbh, cbl, cn, nullptr, nullptr, nullptr, keys);
    gather_q<<<ROWS / 128, 256>>>(keys, cbh, xh, idx_f);

    // ---- decoder (1-pass fp16) ----
    mma_gemm<DV, HV, 1536, 1, 1, 1, 1, HV, 256>
        <<<dim3(HV / 256, ROWS / 128), 256, SM1_256>>>(
        xh, nullptr, wh + OW3, nullptr, db1, yh, nullptr, nullptr, nullptr);
    mma_gemm<HV, INV, 1536, 1, 1, 2, 0, INV, 128>
        <<<dim3(1, ROWS / 128), 256, SM1_128>>>(
        yh, nullptr, wh + OW4, nullptr, db2, nullptr, nullptr, recon, nullptr);
}